// round 15
// baseline (speedup 1.0000x reference)
#include <cuda_runtime.h>
#include <cuda_fp16.h>

// Gridding R14: 2-RED/point fp16x2 parity scatter + combine, pipelined at
// EIGHTH granularity (8 batches/chunk, 16.8 MB buffers) with CTA-level
// fusion so both live buffers + streams stay L2-resident (R13's fused
// pipeline at quarter granularity thrashed L2 -> DRAM RMWs).
// Launch k = scatter(chunk k) + combine(chunk k-1), 4:1 interleaved.

#define GB 64
#define GBC 8                                   // batches per chunk
#define NCHUNK 8
#define GN 65536
#define GS 64
#define GRID_CELLS  (GS * GS * GS)
#define CHUNK_PTS   (GBC * GN)                  // 524288
#define PLANE_WORDS 2048
#define GRID_WORDS  ((size_t)GBC * GS * PLANE_WORDS)  // 1048576 words = 4.2 MB
#define BUF_WORDS   (4 * GRID_WORDS)            // 16.8 MB (4-parity buffer)

// Double-buffered parity scratch. Zero-initialized at load; each combine
// clears the buffer it reads, so every graph replay starts from zeros.
__device__ unsigned int g_S[2 * BUF_WORDS];     // 33.5 MB

// ---------------------------------------------------------------- scatter body
__device__ __forceinline__ void scatter_body(const float* __restrict__ pt,
                                             int buf, int sid) {
    int gid = sid * 256 + threadIdx.x;          // < CHUNK_PTS by construction

    int b = gid >> 16;                          // local batch 0..7

    const float* p3 = pt + (size_t)gid * 3;
    float px = p3[0] * 32.0f;
    float py = p3[1] * 32.0f;
    float pz = p3[2] * 32.0f;

    if (fabsf(px) + fabsf(py) + fabsf(pz) == 0.0f) return;

    float lx = floorf(px), ly = floorf(py), lz = floorf(pz);
    float fx = px - lx, fy = py - ly, fz = pz - lz;

    int ix = (int)lx + 32;                      // uniform input: [0,63]
    int iy = (int)ly + 32;
    int iz = (int)lz + 32;

    float wy0 = 1.0f - fy, wy1 = fy;
    float wz0 = 1.0f - fz, wz1 = fz;

    float a00 = wy0 * wz0, a01 = wy0 * wz1;
    float a10 = wy1 * wz0, a11 = wy1 * wz1;

    int p = ((iy & 1) << 1) | (iz & 1);
    unsigned int* base = g_S + (size_t)buf * BUF_WORDS + (size_t)p * GRID_WORDS;
    int zw = iz >> 1;
    int ypair = iy & ~1;

    float wx[2] = {1.0f - fx, fx};

    #pragma unroll
    for (int i = 0; i < 2; i++) {
        int X = ix + i;
        if (X >= GS) continue;
        float w = wx[i];
        __half2 h0 = __floats2half2_rn(w * a00, w * a01);
        __half2 h1 = __floats2half2_rn(w * a10, w * a11);
        unsigned int r0 = *(unsigned int*)&h0;
        unsigned int r1 = *(unsigned int*)&h1;
        size_t word = (((size_t)(b * GS + X) * 32 + zw) << 6) + ypair;
        asm volatile("red.global.add.noftz.v2.f16x2 [%0], {%1, %2};"
                     :: "l"(base + word), "r"(r0), "r"(r1) : "memory");
    }
}

// ---------------------------------------------------------------- combine body
__device__ __forceinline__ float half_of(unsigned int w, int k) {
    __half2 h = *(__half2*)&w;
    return k ? __high2float(h) : __low2float(h);
}

__device__ __forceinline__ void combine_body(float* __restrict__ out,
                                             int buf, int cid,
                                             unsigned int (*s)[PLANE_WORDS]) {
    int t = threadIdx.x;
    size_t pbase = (size_t)cid * PLANE_WORDS;
    unsigned int* S = g_S + (size_t)buf * BUF_WORDS;

    uint4 v[4][2];
    #pragma unroll
    for (int g = 0; g < 4; g++) {
        uint4* gp = (uint4*)(S + (size_t)g * GRID_WORDS + pbase);
        #pragma unroll
        for (int i = 0; i < 2; i++) v[g][i] = gp[t + i * 256];
    }
    #pragma unroll
    for (int g = 0; g < 4; g++) {
        uint4* sp = (uint4*)s[g];
        uint4* gp = (uint4*)(S + (size_t)g * GRID_WORDS + pbase);
        #pragma unroll
        for (int i = 0; i < 2; i++) {
            sp[t + i * 256] = v[g][i];
            gp[t + i * 256] = make_uint4(0u, 0u, 0u, 0u);
        }
    }
    __syncthreads();

    int Y = t >> 2;
    int Z0 = (t & 3) << 4;

    float res[16];
    #pragma unroll
    for (int i = 0; i < 16; i++) {
        int Z = Z0 + i;
        float r = half_of(s[0][(Z >> 1) * 64 + Y], Z & 1);
        if (Z > 0)
            r += half_of(s[1][((Z - 1) >> 1) * 64 + Y], (Z - 1) & 1);
        if (Y > 0) {
            r += half_of(s[2][(Z >> 1) * 64 + (Y - 1)], Z & 1);
            if (Z > 0)
                r += half_of(s[3][((Z - 1) >> 1) * 64 + (Y - 1)], (Z - 1) & 1);
        }
        res[i] = r;
    }

    float4* o = (float4*)(out + ((size_t)cid * 64 + Y) * 64 + Z0);
    o[0] = make_float4(res[0],  res[1],  res[2],  res[3]);
    o[1] = make_float4(res[4],  res[5],  res[6],  res[7]);
    o[2] = make_float4(res[8],  res[9],  res[10], res[11]);
    o[3] = make_float4(res[12], res[13], res[14], res[15]);
}

// ---------------------------------------------------------------- fused kernel
// mode 0: pure scatter (grid 2048). mode 1: fused 4:1 (grid 2560).
// mode 2: pure combine (grid 512).
__global__ __launch_bounds__(256) void fused_kernel(const float* __restrict__ pt,
                                                    float* __restrict__ out,
                                                    int sbuf, int cbuf, int mode) {
    __shared__ unsigned int s[4][PLANE_WORDS];   // 32 KB (combine paths only)
    int bid = blockIdx.x;

    if (mode == 0) {
        scatter_body(pt, sbuf, bid);
        return;
    }
    if (mode == 2) {
        combine_body(out, cbuf, bid, s);
        return;
    }
    int r = bid % 5;
    int g = bid / 5;
    if (r == 4) combine_body(out, cbuf, g, s);
    else        scatter_body(pt, sbuf, g * 4 + r);
}

extern "C" void kernel_launch(void* const* d_in, const int* in_sizes, int n_in,
                              void* d_out, int out_size) {
    const float* pt = (const float*)d_in[0];
    float* out = (float*)d_out;

    // launch 0: scatter chunk 0 (buf 0)
    fused_kernel<<<CHUNK_PTS / 256, 256>>>(pt, nullptr, 0, 0, 0);

    // launches 1..7: scatter chunk k (buf k&1) + combine chunk k-1
    for (int k = 1; k < NCHUNK; k++) {
        const float* ptk = pt + (size_t)k * GBC * GN * 3;
        float* outp = out + (size_t)(k - 1) * GBC * GRID_CELLS;
        fused_kernel<<<CHUNK_PTS / 256 + GBC * GS, 256>>>(ptk, outp,
                                                          k & 1, (k - 1) & 1, 1);
    }

    // tail: combine chunk 7 (buf 1)
    fused_kernel<<<GBC * GS, 256>>>(nullptr,
                                    out + (size_t)(NCHUNK - 1) * GBC * GRID_CELLS,
                                    0, 1, 2);
}

// round 16
// speedup vs baseline: 1.3961x; 1.3961x over previous
#include <cuda_runtime.h>
#include <cuda_fp16.h>

// Gridding R15: R10 serial quarter pipeline (best: 119.2us) + cache-policy
// hygiene: evict-first (.cs) for all single-use streaming traffic so L2
// retention is reserved for the scratch lines that live across launches.
// Overlap variants (R12-R14) all regressed; serial keeps the hot set in L2.

#define GB 64
#define GBQ 16
#define GN 65536
#define GS 64
#define GRID_CELLS  (GS * GS * GS)
#define QTR_PTS     (GBQ * GN)                  // 1048576
#define PLANE_WORDS 2048
#define GRID_WORDS  ((size_t)GBQ * GS * PLANE_WORDS)  // 2097152 words = 8.4 MB

// 4 parity grids (p = ((iy&1)<<1)|(iz&1)) for ONE quarter of the batches.
// Zero-initialized at load; combine re-zeroes everything it reads.
__device__ unsigned int g_S[4 * GRID_WORDS];    // 33.5 MB

// ---------------------------------------------------------------- scatter
__global__ __launch_bounds__(256) void scatter_kernel(const float* __restrict__ pt) {
    int gid = blockIdx.x * blockDim.x + threadIdx.x;
    if (gid >= QTR_PTS) return;

    int b = gid >> 16;                          // local batch 0..15

    const float* p3 = pt + (size_t)gid * 3;
    float px = __ldcs(p3 + 0) * 32.0f;          // streamed once: evict-first
    float py = __ldcs(p3 + 1) * 32.0f;
    float pz = __ldcs(p3 + 2) * 32.0f;

    if (fabsf(px) + fabsf(py) + fabsf(pz) == 0.0f) return;

    float lx = floorf(px), ly = floorf(py), lz = floorf(pz);
    float fx = px - lx, fy = py - ly, fz = pz - lz;

    int ix = (int)lx + 32;                      // uniform input: [0,63]
    int iy = (int)ly + 32;
    int iz = (int)lz + 32;

    float wy0 = 1.0f - fy, wy1 = fy;
    float wz0 = 1.0f - fz, wz1 = fz;

    float a00 = wy0 * wz0, a01 = wy0 * wz1;
    float a10 = wy1 * wz0, a11 = wy1 * wz1;

    int p = ((iy & 1) << 1) | (iz & 1);
    unsigned int* base = g_S + (size_t)p * GRID_WORDS;
    int zw = iz >> 1;
    int ypair = iy & ~1;

    float wx[2] = {1.0f - fx, fx};

    #pragma unroll
    for (int i = 0; i < 2; i++) {
        int X = ix + i;
        if (X >= GS) continue;
        float w = wx[i];
        __half2 h0 = __floats2half2_rn(w * a00, w * a01);
        __half2 h1 = __floats2half2_rn(w * a10, w * a11);
        unsigned int r0 = *(unsigned int*)&h0;
        unsigned int r1 = *(unsigned int*)&h1;
        size_t word = (((size_t)(b * GS + X) * 32 + zw) << 6) + ypair;
        asm volatile("red.global.add.noftz.v2.f16x2 [%0], {%1, %2};"
                     :: "l"(base + word), "r"(r0), "r"(r1) : "memory");
    }
}

// ---------------------------------------------------------------- combine
__device__ __forceinline__ float half_of(unsigned int w, int k) {
    __half2 h = *(__half2*)&w;
    return k ? __high2float(h) : __low2float(h);
}

__global__ __launch_bounds__(256) void combine_kernel(float* __restrict__ out) {
    __shared__ unsigned int s[4][PLANE_WORDS];
    int cta = blockIdx.x;                       // b_local*64 + X
    int t = threadIdx.x;
    size_t pbase = (size_t)cta * PLANE_WORDS;

    // Scratch reads: each line is consumed once here (then overwritten by
    // the clear) -> evict-first. Clear stores keep default policy: those
    // lines must stay resident for the next quarter's scatter REDs.
    uint4 v[4][2];
    #pragma unroll
    for (int g = 0; g < 4; g++) {
        const uint4* gp = (const uint4*)(g_S + (size_t)g * GRID_WORDS + pbase);
        #pragma unroll
        for (int i = 0; i < 2; i++) v[g][i] = __ldcs(gp + t + i * 256);
    }
    #pragma unroll
    for (int g = 0; g < 4; g++) {
        uint4* sp = (uint4*)s[g];
        uint4* gp = (uint4*)(g_S + (size_t)g * GRID_WORDS + pbase);
        #pragma unroll
        for (int i = 0; i < 2; i++) {
            sp[t + i * 256] = v[g][i];
            gp[t + i * 256] = make_uint4(0u, 0u, 0u, 0u);
        }
    }
    __syncthreads();

    int Y = t >> 2;
    int Z0 = (t & 3) << 4;

    float res[16];
    #pragma unroll
    for (int i = 0; i < 16; i++) {
        int Z = Z0 + i;
        float r = half_of(s[0][(Z >> 1) * 64 + Y], Z & 1);
        if (Z > 0)
            r += half_of(s[1][((Z - 1) >> 1) * 64 + Y], (Z - 1) & 1);
        if (Y > 0) {
            r += half_of(s[2][(Z >> 1) * 64 + (Y - 1)], Z & 1);
            if (Z > 0)
                r += half_of(s[3][((Z - 1) >> 1) * 64 + (Y - 1)], (Z - 1) & 1);
        }
        res[i] = r;
    }

    // Output is write-once, never re-read on device -> evict-first.
    float4* o = (float4*)(out + ((size_t)cta * 64 + Y) * 64 + Z0);
    __stcs(o + 0, make_float4(res[0],  res[1],  res[2],  res[3]));
    __stcs(o + 1, make_float4(res[4],  res[5],  res[6],  res[7]));
    __stcs(o + 2, make_float4(res[8],  res[9],  res[10], res[11]));
    __stcs(o + 3, make_float4(res[12], res[13], res[14], res[15]));
}

extern "C" void kernel_launch(void* const* d_in, const int* in_sizes, int n_in,
                              void* d_out, int out_size) {
    const float* pt = (const float*)d_in[0];
    float* out = (float*)d_out;

    int threads = 256;
    int sblocks = (QTR_PTS + threads - 1) / threads;

    for (int q = 0; q < 4; q++) {
        const float* ptq = pt + (size_t)q * GBQ * GN * 3;
        float* outq = out + (size_t)q * GBQ * GRID_CELLS;
        scatter_kernel<<<sblocks, threads>>>(ptq);
        combine_kernel<<<GBQ * GS, 256>>>(outq);
    }
}